// round 5
// baseline (speedup 1.0000x reference)
#include <cuda_runtime.h>
#include <math.h>

#define NN 4096
#define EE 131072
#define PCH 3
#define FINN 128
#define F1 16
#define F2 4
#define SEGS 24

// ---------------- scratch (device globals; no allocation allowed) ----------------
__device__ float g_h1[NN * F1];
__device__ float g_hs1[NN], g_hd1[NN];
__device__ float g_ae[EE * PCH];
__device__ float g_h2[NN * F2];
__device__ float g_hs2[NN], g_hd2[NN];
__device__ float g_hfinal[NN * (PCH * F2)];  // elu'd layer2 output [N,12]
__device__ int   g_cnt[NN];                  // self-resetting histogram
__device__ int   g_off[NN + 1];
__device__ int   g_cursor[NN];
__device__ int   g_eidx[EE];
__device__ float g_s1[NN * F1];
__device__ float g_Tpart[SEGS * PCH * F1 * NN];  // 24 segment-partials of s1^T adj (18.9MB)
__device__ float g_x2[F1 * (PCH * F2)];      // [16,12]
__device__ float g_adj1[PCH * F1 * F1];      // [3,16,16]
__device__ float g_G[F1 * F1];               // s1^T s1
__device__ float g_entp[16];                 // entropy partials
__device__ float g_sqp[576];                 // adj^2 partials (per bigadj block)
__device__ float g_crossp[48];               // cross partials

__device__ __forceinline__ float lrelu(float v) { return v > 0.f ? v : 0.2f * v; }
__device__ __forceinline__ float elu(float v)   { return v > 0.f ? v : expm1f(v); }

#define FMA2(d, a, b) asm("fma.rn.f32x2 %0, %1, %2, %3;" : "=l"(d) : "l"(a), "l"(b), "l"(d))
#define DUP32(d, s)   asm("mov.b64 %0, {%1, %1};" : "=l"(d) : "r"(s))
#define LO_F(x) __uint_as_float((unsigned)((x) & 0xffffffffULL))
#define HI_F(x) __uint_as_float((unsigned)((x) >> 32))

// ================= k_front =================
// blocks [0,16): softmax(S1) rows + entropy partials
// blocks [16,144): gemm1 (h1 = x@W1, hs1, hd1), 32 rows each
// blocks [144,272): histogram of dst into g_cnt (1024 edges each)
__global__ void k_front(const float* __restrict__ S1,
                        const float* __restrict__ x, const float* __restrict__ W1,
                        const float* __restrict__ a1s, const float* __restrict__ a1d,
                        const int* __restrict__ dst) {
    int b = blockIdx.x, t = threadIdx.x;
    if (b < 16) {
        int r = b * 256 + t;
        float v[16];
        float m = -1e30f;
#pragma unroll
        for (int c = 0; c < 16; c++) { v[c] = S1[r * 16 + c]; m = fmaxf(m, v[c]); }
        float s = 0.f;
#pragma unroll
        for (int c = 0; c < 16; c++) { v[c] = expf(v[c] - m); s += v[c]; }
        float inv = 1.f / s;
        float ent = 0.f;
#pragma unroll
        for (int c = 0; c < 16; c++) {
            float p = v[c] * inv;
            g_s1[r * 16 + c] = p;
            ent -= p * logf(p + 1e-15f);
        }
        __shared__ float red[256];
        red[t] = ent;
        __syncthreads();
        for (int o = 128; o > 0; o >>= 1) { if (t < o) red[t] += red[t + o]; __syncthreads(); }
        if (t == 0) g_entp[b] = red[0];
    } else if (b < 144) {
        int n0 = (b - 16) * 32;
        __shared__ float sx[32 * 132];        // 32 rows x 128, stride 132 (bank-pad)
        __shared__ float sw[FINN * F1];
        for (int u = t; u < 1024; u += 256) {
            int r = u >> 5, c4 = u & 31;
            float4 xv = ((const float4*)x)[(size_t)(n0 + r) * 32 + c4];
            float* d = &sx[r * 132 + c4 * 4];
            d[0] = xv.x; d[1] = xv.y; d[2] = xv.z; d[3] = xv.w;
        }
        for (int u = t; u < 2048; u += 256) sw[u] = W1[u];
        __syncthreads();
        int r = t >> 3, c = t & 7;
        float a0 = 0.f, a1 = 0.f;
#pragma unroll 8
        for (int k = 0; k < FINN; k++) {
            float xv = sx[r * 132 + k];
            a0 += xv * sw[k * 16 + c];
            a1 += xv * sw[k * 16 + c + 8];
        }
        int n = n0 + r;
        g_h1[n * 16 + c] = a0;
        g_h1[n * 16 + c + 8] = a1;
        float ps = a0 * __ldg(&a1s[c]) + a1 * __ldg(&a1s[c + 8]);
        float pd = a0 * __ldg(&a1d[c]) + a1 * __ldg(&a1d[c + 8]);
#pragma unroll
        for (int o = 1; o < 8; o <<= 1) {
            ps += __shfl_xor_sync(0xffffffff, ps, o);
            pd += __shfl_xor_sync(0xffffffff, pd, o);
        }
        if (c == 0) { g_hs1[n] = ps; g_hd1[n] = pd; }
    } else {
        int e0 = (b - 144) * 1024 + t;
#pragma unroll
        for (int k = 0; k < 4; k++) atomicAdd(&g_cnt[dst[e0 + k * 256]], 1);
    }
}

// ================= scan: offsets + cursors ; resets g_cnt for next replay =================
__global__ void k_scan() {
    int t = threadIdx.x;
    int lane = t & 31, warp = t >> 5;
    int4 c = ((const int4*)g_cnt)[t];
    ((int4*)g_cnt)[t] = make_int4(0, 0, 0, 0);   // reset for next call
    int s = c.x + c.y + c.z + c.w;
    int v = s;
#pragma unroll
    for (int o = 1; o < 32; o <<= 1) {
        int u = __shfl_up_sync(0xffffffff, v, o);
        if (lane >= o) v += u;
    }
    __shared__ int wsum[32];
    if (lane == 31) wsum[warp] = v;
    __syncthreads();
    if (warp == 0) {
        int w = wsum[lane];
#pragma unroll
        for (int o = 1; o < 32; o <<= 1) {
            int u = __shfl_up_sync(0xffffffff, w, o);
            if (lane >= o) w += u;
        }
        wsum[lane] = w;
    }
    __syncthreads();
    int excl = v - s + (warp > 0 ? wsum[warp - 1] : 0);
    int base = t * 4;
    g_off[base] = excl;     g_cursor[base] = excl;     excl += c.x;
    g_off[base + 1] = excl; g_cursor[base + 1] = excl; excl += c.y;
    g_off[base + 2] = excl; g_cursor[base + 2] = excl; excl += c.z;
    g_off[base + 3] = excl; g_cursor[base + 3] = excl;
    if (t == 1023) g_off[NN] = EE;
}

__global__ void k_scatter(const int* __restrict__ dst) {
    int e = blockIdx.x * blockDim.x + threadIdx.x;
    int pos = atomicAdd(&g_cursor[dst[e]], 1);
    g_eidx[pos] = e;
}

// ================= the big one: single wave, 50% occ, 3-stage pipelined =================
// grid 576 = SEGS(24) x (3p x 8col). 256 threads; thread owns 2 floats (8B) of j.
__global__ void __launch_bounds__(256, 4) k_bigadj(const float* __restrict__ adj) {
    int bid = blockIdx.x;
    int seg = bid / 24;
    int pc = bid % 24;
    int p = pc >> 3, col = pc & 7;
    int i_beg = (NN * seg) / SEGS, i_end = (NN * (seg + 1)) / SEGS;
    int jl = col * 256 + threadIdx.x;               // ulonglong (8B) index within row
    __shared__ ulonglong2 stile[64][4];             // 64 rows x 16 s-floats (4KB)

    unsigned long long acc[2][8];                   // [float f of pair][n-pair q]
#pragma unroll
    for (int f = 0; f < 2; f++)
#pragma unroll
        for (int q = 0; q < 8; q++) acc[f][q] = 0ULL;
    unsigned long long sq = 0ULL;

    const unsigned long long* base =
        (const unsigned long long*)(adj + (size_t)p * NN * NN) + jl;

    for (int ib = i_beg; ib < i_end; ib += 64) {
        int cnt = min(64, i_end - ib);
        __syncthreads();
        for (int u = threadIdx.x; u < cnt * 4; u += 256)
            stile[u >> 2][u & 3] = ((const ulonglong2*)g_s1)[(size_t)(ib + (u >> 2)) * 4 + (u & 3)];
        __syncthreads();
        const unsigned long long* rp = base + (size_t)ib * 2048;
        int steps = cnt >> 1;
        unsigned long long A0 = 0, A1 = 0, B0 = 0, B1 = 0;
        if (steps > 0) { A0 = rp[0]; A1 = rp[2048]; }
        if (steps > 1) { B0 = rp[4096]; B1 = rp[6144]; }
#pragma unroll 1
        for (int s = 0; s < steps; s++) {
            unsigned long long C0 = 0, C1 = 0;
            if (s + 2 < steps) {
                C0 = rp[(size_t)(2 * s + 4) * 2048];
                C1 = rp[(size_t)(2 * s + 5) * 2048];
            }
#pragma unroll
            for (int r = 0; r < 2; r++) {
                unsigned long long a = r ? A1 : A0;
                int row = 2 * s + r;
                FMA2(sq, a, a);
                unsigned long long D0, D1;
                DUP32(D0, (unsigned)(a & 0xffffffffULL));
                DUP32(D1, (unsigned)(a >> 32));
                {   // first 4 n-pairs
                    ulonglong2 s01 = stile[row][0], s23 = stile[row][1];
                    unsigned long long P[4] = {s01.x, s01.y, s23.x, s23.y};
#pragma unroll
                    for (int q = 0; q < 4; q++) { FMA2(acc[0][q], D0, P[q]); FMA2(acc[1][q], D1, P[q]); }
                }
                {   // last 4 n-pairs
                    ulonglong2 s45 = stile[row][2], s67 = stile[row][3];
                    unsigned long long P[4] = {s45.x, s45.y, s67.x, s67.y};
#pragma unroll
                    for (int q = 0; q < 4; q++) { FMA2(acc[0][q + 4], D0, P[q]); FMA2(acc[1][q + 4], D1, P[q]); }
                }
            }
            A0 = B0; A1 = B1; B0 = C0; B1 = C1;
        }
        if (cnt & 1) {
            int row = cnt - 1;
            unsigned long long a = rp[(size_t)row * 2048];
            FMA2(sq, a, a);
            unsigned long long D0, D1;
            DUP32(D0, (unsigned)(a & 0xffffffffULL));
            DUP32(D1, (unsigned)(a >> 32));
            ulonglong2 s01 = stile[row][0], s23 = stile[row][1];
            ulonglong2 s45 = stile[row][2], s67 = stile[row][3];
            unsigned long long P[8] = {s01.x, s01.y, s23.x, s23.y, s45.x, s45.y, s67.x, s67.y};
#pragma unroll
            for (int q = 0; q < 8; q++) { FMA2(acc[0][q], D0, P[q]); FMA2(acc[1][q], D1, P[q]); }
        }
    }

    // stores: acc[f][q] = (T[2q][j0+f], T[2q+1][j0+f]); coalesced float2, no atomics
    float* Tp = g_Tpart + ((size_t)(seg * 3 + p) * 16) * NN;
    int j0 = jl * 2;
#pragma unroll
    for (int q = 0; q < 8; q++) {
        float2 v0, v1;
        v0.x = LO_F(acc[0][q]); v0.y = LO_F(acc[1][q]);
        v1.x = HI_F(acc[0][q]); v1.y = HI_F(acc[1][q]);
        *(float2*)&Tp[(2 * q) * NN + j0] = v0;
        *(float2*)&Tp[(2 * q + 1) * NN + j0] = v1;
    }
    float sqf = LO_F(sq) + HI_F(sq);
#pragma unroll
    for (int o = 16; o > 0; o >>= 1) sqf += __shfl_xor_sync(0xffffffff, sqf, o);
    __shared__ float sred[8];
    if ((threadIdx.x & 31) == 0) sred[threadIdx.x >> 5] = sqf;
    __syncthreads();
    if (threadIdx.x == 0) {
        float tot = 0.f;
#pragma unroll
        for (int w = 0; w < 8; w++) tot += sred[w];
        g_sqp[bid] = tot;
    }
}

// ================= agg1: warp-per-node, inline score + softmax + agg + fused gemm2 =======
__global__ void k_agg1(const int* __restrict__ src, const float* __restrict__ eattr,
                       const float* __restrict__ W2, const float* __restrict__ a2s,
                       const float* __restrict__ a2d) {
    int w = threadIdx.x >> 5, lane = threadIdx.x & 31;
    int n = blockIdx.x * 8 + w;
    int s0 = g_off[n], deg = g_off[n + 1] - s0;
    float hd1n = g_hd1[n];
    float m = -1e30f;
    for (int k = lane; k < deg; k += 32)
        m = fmaxf(m, lrelu(g_hs1[src[g_eidx[s0 + k]]] + hd1n));
#pragma unroll
    for (int o = 16; o > 0; o >>= 1) m = fmaxf(m, __shfl_xor_sync(0xffffffff, m, o));
    float d = 0.f;
    for (int k = lane; k < deg; k += 32)
        d += expf(lrelu(g_hs1[src[g_eidx[s0 + k]]] + hd1n) - m);
#pragma unroll
    for (int o = 16; o > 0; o >>= 1) d += __shfl_xor_sync(0xffffffff, d, o);
    float inv = 1.f / d;
    __shared__ float sa[8][3][32];
    __shared__ int   ss[8][32];
    float acc0 = 0.f, acc1 = 0.f;
    int p1 = lane >> 4, f1 = lane & 15;          // output o1 = lane
    for (int base = 0; base < deg; base += 32) {
        int k = base + lane;
        if (k < deg) {
            int e = g_eidx[s0 + k];
            int sr = src[e];
            float al = expf(lrelu(g_hs1[sr] + hd1n) - m) * inv;
            float a0 = al * eattr[e * 3 + 0];
            float a1 = al * eattr[e * 3 + 1];
            float a2v = al * eattr[e * 3 + 2];
            sa[w][0][lane] = a0; sa[w][1][lane] = a1; sa[w][2][lane] = a2v;
            ss[w][lane] = sr;
            g_ae[e * 3 + 0] = a0; g_ae[e * 3 + 1] = a1; g_ae[e * 3 + 2] = a2v;
        }
        __syncwarp();
        int lim = min(32, deg - base);
        for (int kk = 0; kk < lim; kk++) {
            int sr = ss[w][kk];
            acc0 += sa[w][p1][kk] * g_h1[sr * 16 + f1];
            if (lane < 16) acc1 += sa[w][2][kk] * g_h1[sr * 16 + lane];
        }
        __syncwarp();
    }
    __shared__ float sh[8][48];
    sh[w][lane] = elu(acc0);
    if (lane < 16) sh[w][32 + lane] = elu(acc1);
    __syncwarp();
    if (lane < 4) {
        float v = 0.f;
#pragma unroll
        for (int k = 0; k < 48; k++) v += sh[w][k] * W2[k * 4 + lane];
        g_h2[n * 4 + lane] = v;
        float vs = v * __ldg(&a2s[lane]), vd = v * __ldg(&a2d[lane]);
        vs += __shfl_xor_sync(0xf, vs, 1); vs += __shfl_xor_sync(0xf, vs, 2);
        vd += __shfl_xor_sync(0xf, vd, 1); vd += __shfl_xor_sync(0xf, vd, 2);
        if (lane == 0) { g_hs2[n] = vs; g_hd2[n] = vd; }
    }
}

// ================= agg2: warp-per-node =================
__global__ void k_agg2(const int* __restrict__ src) {
    int w = threadIdx.x >> 5, lane = threadIdx.x & 31;
    int n = blockIdx.x * 8 + w;
    int s0 = g_off[n], deg = g_off[n + 1] - s0;
    float hd2n = g_hd2[n];
    float m = -1e30f;
    for (int k = lane; k < deg; k += 32)
        m = fmaxf(m, lrelu(g_hs2[src[g_eidx[s0 + k]]] + hd2n));
#pragma unroll
    for (int o = 16; o > 0; o >>= 1) m = fmaxf(m, __shfl_xor_sync(0xffffffff, m, o));
    float d = 0.f;
    for (int k = lane; k < deg; k += 32)
        d += expf(lrelu(g_hs2[src[g_eidx[s0 + k]]] + hd2n) - m);
#pragma unroll
    for (int o = 16; o > 0; o >>= 1) d += __shfl_xor_sync(0xffffffff, d, o);
    float inv = 1.f / d;
    __shared__ float swt[8][3][32];
    __shared__ int   ss2[8][32];
    float acc = 0.f;
    int p = lane >> 2, f = lane & 3;             // lane<12 => output o = lane
    for (int base = 0; base < deg; base += 32) {
        int k = base + lane;
        if (k < deg) {
            int e = g_eidx[s0 + k];
            int sr = src[e];
            float al = expf(lrelu(g_hs2[sr] + hd2n) - m) * inv;
            swt[w][0][lane] = al * g_ae[e * 3 + 0];
            swt[w][1][lane] = al * g_ae[e * 3 + 1];
            swt[w][2][lane] = al * g_ae[e * 3 + 2];
            ss2[w][lane] = sr;
        }
        __syncwarp();
        int lim = min(32, deg - base);
        if (lane < 12) {
            for (int kk = 0; kk < lim; kk++)
                acc += swt[w][p][kk] * g_h2[ss2[w][kk] * 4 + f];
        }
        __syncwarp();
    }
    if (lane < 12) g_hfinal[n * 12 + lane] = elu(acc);
}

// ================= reduce: [0,48) adj1+cross ; [48,240) x2 ; [240,496) G =================
__global__ void k_reduce() {
    int b = blockIdx.x, t = threadIdx.x;
    if (b < 48) {
        int p = b / 16, n = b % 16;
        float accm[16];
#pragma unroll
        for (int m = 0; m < 16; m++) accm[m] = 0.f;
        for (int j = t; j < NN; j += 256) {
            float tv = 0.f;
#pragma unroll
            for (int s = 0; s < SEGS; s++)
                tv += g_Tpart[(((size_t)s * 3 + p) * 16 + n) * NN + j];
            const float4* s4 = (const float4*)(g_s1 + (size_t)j * 16);
            float4 sa = s4[0], sb = s4[1], sc = s4[2], sd = s4[3];
            accm[0] += tv * sa.x; accm[1] += tv * sa.y; accm[2] += tv * sa.z; accm[3] += tv * sa.w;
            accm[4] += tv * sb.x; accm[5] += tv * sb.y; accm[6] += tv * sb.z; accm[7] += tv * sb.w;
            accm[8] += tv * sc.x; accm[9] += tv * sc.y; accm[10] += tv * sc.z; accm[11] += tv * sc.w;
            accm[12] += tv * sd.x; accm[13] += tv * sd.y; accm[14] += tv * sd.z; accm[15] += tv * sd.w;
        }
#pragma unroll
        for (int m = 0; m < 16; m++)
#pragma unroll
            for (int o = 16; o > 0; o >>= 1) accm[m] += __shfl_xor_sync(0xffffffff, accm[m], o);
        __shared__ float wred[8][16];
        if ((t & 31) == 0) {
#pragma unroll
            for (int m = 0; m < 16; m++) wred[t >> 5][m] = accm[m];
        }
        __syncthreads();
        if (t < 16) {
            float s = 0.f;
#pragma unroll
            for (int w = 0; w < 8; w++) s += wred[w][t];
            g_adj1[b * 16 + t] = s;
            if (t == n) g_crossp[b] = s;      // cross contribution = diag(adj1)
        }
    } else {
        __shared__ float red[256];
        float s = 0.f;
        if (b < 240) {
            int b2 = b - 48;
            int n = b2 / 12, f = b2 % 12;
            for (int i = t; i < NN; i += 256) s += g_s1[i * 16 + n] * g_hfinal[i * 12 + f];
        } else {
            int b2 = b - 240;
            int n = b2 >> 4, m2 = b2 & 15;
            for (int i = t; i < NN; i += 256) s += g_s1[i * 16 + n] * g_s1[i * 16 + m2];
        }
        red[t] = s; __syncthreads();
        for (int o = 128; o > 0; o >>= 1) { if (t < o) red[t] += red[t + o]; __syncthreads(); }
        if (t == 0) {
            if (b < 240) g_x2[b - 48] = red[0];
            else g_G[b - 240] = red[0];
        }
    }
}

// ================= final: partial sums, losses, MLP =================
__global__ void k_final(const float* __restrict__ fc1w, const float* __restrict__ fc1b,
                        const float* __restrict__ fc2w, const float* __restrict__ fc2b,
                        const float* __restrict__ fc3w, const float* __restrict__ fc3b,
                        const float* __restrict__ fc4w, const float* __restrict__ fc4b,
                        float* __restrict__ out, int out_size) {
    int t = threadIdx.x;   // 256 threads
    __shared__ float red[256];
    __shared__ float s_adjsq, s_ent, s_cross, s_sst, s_l2;
    __shared__ float x3[12];
    float s;
    s = 0.f; for (int i = t; i < 576; i += 256) s += g_sqp[i];
    red[t] = s; __syncthreads();
    for (int o = 128; o > 0; o >>= 1) { if (t < o) red[t] += red[t + o]; __syncthreads(); }
    if (t == 0) s_adjsq = red[0];
    __syncthreads();
    s = (t < 16) ? g_entp[t] : 0.f;
    red[t] = s; __syncthreads();
    for (int o = 128; o > 0; o >>= 1) { if (t < o) red[t] += red[t + o]; __syncthreads(); }
    if (t == 0) s_ent = red[0];
    __syncthreads();
    s = (t < 48) ? g_crossp[t] : 0.f;
    red[t] = s; __syncthreads();
    for (int o = 128; o > 0; o >>= 1) { if (t < o) red[t] += red[t + o]; __syncthreads(); }
    if (t == 0) s_cross = red[0];
    __syncthreads();
    s = g_G[t] * g_G[t];
    red[t] = s; __syncthreads();
    for (int o = 128; o > 0; o >>= 1) { if (t < o) red[t] += red[t + o]; __syncthreads(); }
    if (t == 0) s_sst = red[0];
    __syncthreads();
    s = 0.f; for (int i = t; i < 768; i += 256) { float a = g_adj1[i] - 1.f; s += a * a; }
    red[t] = s; __syncthreads();
    for (int o = 128; o > 0; o >>= 1) { if (t < o) red[t] += red[t + o]; __syncthreads(); }
    if (t == 0) s_l2 = red[0];
    if (t < 12) {
        float v = 0.f;
        for (int n = 0; n < 16; n++) v += g_x2[n * 12 + t];
        x3[t] = v;
    }
    __syncthreads();
    if (t == 0) {
        float denom1 = (float)PCH * (float)NN * (float)NN;
        float link1 = sqrtf(fmaxf(s_adjsq - 2.f * s_cross + 3.f * s_sst, 0.f)) / denom1;
        float ent1 = s_ent / (float)NN;
        float link2 = sqrtf(s_l2) / (float)(PCH * F1 * F1);
        float ent2 = -logf(1.0f + 1e-15f);
        float r = link1 + ent1 + link2 + ent2;
        float z1[20], z2[20];
        for (int o = 0; o < 20; o++) {
            float a = fc1b[o];
            for (int k = 0; k < 12; k++) a += x3[k] * fc1w[k * 20 + o];
            z1[o] = elu(a);
        }
        for (int o = 0; o < 16; o++) {
            float a = fc2b[o];
            for (int k = 0; k < 20; k++) a += z1[k] * fc2w[k * 16 + o];
            z2[o] = elu(a);
        }
        for (int o = 0; o < 20; o++) {
            float a = fc3b[o];
            for (int k = 0; k < 16; k++) a += z2[k] * fc3w[k * 20 + o];
            z1[o] = elu(a);
        }
        float o0 = fc4b[0], o1 = fc4b[1];
        for (int k = 0; k < 20; k++) { o0 += z1[k] * fc4w[k * 2 + 0]; o1 += z1[k] * fc4w[k * 2 + 1]; }
        if (out_size >= 1) out[0] = o0;
        if (out_size >= 2) out[1] = o1;
        if (out_size >= 3) out[2] = r;
    }
}

// ---------------- launch ----------------
extern "C" void kernel_launch(void* const* d_in, const int* in_sizes, int n_in,
                              void* d_out, int out_size) {
    const float* x    = (const float*)d_in[0];
    const int*   eidx = (const int*)d_in[1];
    const float* eat  = (const float*)d_in[2];
    const float* adj  = (const float*)d_in[3];
    const float* W1   = (const float*)d_in[4];
    const float* a1s  = (const float*)d_in[5];
    const float* a1d  = (const float*)d_in[6];
    const float* W2   = (const float*)d_in[7];
    const float* a2s  = (const float*)d_in[8];
    const float* a2d  = (const float*)d_in[9];
    const float* S1   = (const float*)d_in[10];
    const float* fc1w = (const float*)d_in[12];
    const float* fc1b = (const float*)d_in[13];
    const float* fc2w = (const float*)d_in[14];
    const float* fc2b = (const float*)d_in[15];
    const float* fc3w = (const float*)d_in[16];
    const float* fc3b = (const float*)d_in[17];
    const float* fc4w = (const float*)d_in[18];
    const float* fc4b = (const float*)d_in[19];
    const int* src = eidx;
    const int* dst = eidx + EE;
    float* out = (float*)d_out;

    k_front<<<272, 256>>>(S1, x, W1, a1s, a1d, dst);
    k_scan<<<1, 1024>>>();
    k_scatter<<<EE / 256, 256>>>(dst);
    k_bigadj<<<576, 256>>>(adj);           // 4th launch -> profiled by ncu slot
    k_agg1<<<NN / 8, 256>>>(src, eat, W2, a2s, a2d);
    k_agg2<<<NN / 8, 256>>>(src);
    k_reduce<<<496, 256>>>();
    k_final<<<1, 256>>>(fc1w, fc1b, fc2w, fc2b, fc3w, fc3b, fc4w, fc4b, out, out_size);
}